// round 2
// baseline (speedup 1.0000x reference)
#include <cuda_runtime.h>
#include <math.h>

#define B_ 16
#define N_ 2048
#define D_ 256
#define K_ 8
#define H_ 4
#define HID_ 1024
#define LN_EPS 1e-5f
#define SCALEF 0.0625f   // 256^-0.5

// ------------------- static device scratch (no allocations) -------------------
static __device__ float g_emb  [B_*N_*D_];        // LayerNorm'd embeddings (33.5 MB, L2-resident)
static __device__ float g_slots[B_*K_*D_];
static __device__ float g_w    [B_*D_*K_*H_];     // folded key*query weights, [b][e][k*4+h]
static __device__ float g_aggp [B_*16*K_*D_];     // per-token-tile partial attn@emb
static __device__ float g_rsp  [B_*16*K_];        // per-token-tile partial rowsums
static __device__ float g_upd  [B_*K_*D_];
static __device__ float g_gi   [B_*K_*3*D_];
static __device__ float g_gh   [B_*K_*3*D_];
static __device__ float g_pre  [B_*K_*D_];
static __device__ float g_hid  [B_*K_*HID_];

// ------------------- slots = mu + exp(logsigma)*noise -------------------
__global__ void k_init_slots(const float* __restrict__ mu, const float* __restrict__ ls,
                             const float* __restrict__ nz) {
    int i = blockIdx.x * 256 + threadIdx.x;          // 32768
    int kd = i & (K_*D_ - 1);
    g_slots[i] = mu[kd] + __expf(ls[kd]) * nz[i];
}

// ------------------- row LayerNorm (one warp per 256-wide row) -------------------
// mode 0: x=xin -> g_emb ; mode 1: x=g_slots -> g_pre
__global__ __launch_bounds__(256) void k_lnrow(const float* __restrict__ xin,
                                               const float* __restrict__ g,
                                               const float* __restrict__ b, int mode) {
    int wid = threadIdx.x >> 5, lane = threadIdx.x & 31;
    size_t row = (size_t)blockIdx.x * 8 + wid;
    const float* x  = (mode == 0) ? xin : g_slots;
    float*       out = (mode == 0) ? g_emb : g_pre;
    const float* xr = x + row * D_;
    float4 v0 = ((const float4*)xr)[lane];
    float4 v1 = ((const float4*)xr)[32 + lane];
    float s = v0.x+v0.y+v0.z+v0.w + v1.x+v1.y+v1.z+v1.w;
    float q = v0.x*v0.x+v0.y*v0.y+v0.z*v0.z+v0.w*v0.w
            + v1.x*v1.x+v1.y*v1.y+v1.z*v1.z+v1.w*v1.w;
    #pragma unroll
    for (int o = 16; o; o >>= 1) {
        s += __shfl_xor_sync(0xffffffffu, s, o);
        q += __shfl_xor_sync(0xffffffffu, q, o);
    }
    float m  = s * (1.0f / D_);
    float rs = rsqrtf(q * (1.0f / D_) - m * m + LN_EPS);
    float4 g0 = ((const float4*)g)[lane],      b0 = ((const float4*)b)[lane];
    float4 g1 = ((const float4*)g)[32 + lane], b1 = ((const float4*)b)[32 + lane];
    float4 o0, o1;
    o0.x = (v0.x-m)*rs*g0.x + b0.x;  o0.y = (v0.y-m)*rs*g0.y + b0.y;
    o0.z = (v0.z-m)*rs*g0.z + b0.z;  o0.w = (v0.w-m)*rs*g0.w + b0.w;
    o1.x = (v1.x-m)*rs*g1.x + b1.x;  o1.y = (v1.y-m)*rs*g1.y + b1.y;
    o1.z = (v1.z-m)*rs*g1.z + b1.z;  o1.w = (v1.w-m)*rs*g1.w + b1.w;
    ((float4*)(out + row * D_))[lane]      = o0;
    ((float4*)(out + row * D_))[32 + lane] = o1;
}

// ------------------- per (b,k): LN(slots) -> q=diag(to_queries)*s -> w = SCALE*tk@q -------------------
__global__ __launch_bounds__(256) void k_w(const float* __restrict__ tq,
                                           const float* __restrict__ tk,
                                           const float* __restrict__ lg,
                                           const float* __restrict__ lb) {
    __shared__ float q_sh[D_];
    __shared__ float red[16];
    int bk = blockIdx.x, b = bk >> 3, k = bk & 7, t = threadIdx.x;
    float x = g_slots[(size_t)bk * D_ + t];
    float s = x, q = x * x;
    #pragma unroll
    for (int o = 16; o; o >>= 1) {
        s += __shfl_xor_sync(0xffffffffu, s, o);
        q += __shfl_xor_sync(0xffffffffu, q, o);
    }
    if ((t & 31) == 0) { red[t >> 5] = s; red[8 + (t >> 5)] = q; }
    __syncthreads();
    float S = 0.0f, Q = 0.0f;
    #pragma unroll
    for (int i = 0; i < 8; i++) { S += red[i]; Q += red[8 + i]; }
    float m  = S * (1.0f / D_);
    float rs = rsqrtf(Q * (1.0f / D_) - m * m + LN_EPS);
    float sv = (x - m) * rs * lg[t] + lb[t];
    q_sh[t] = sv * tq[(size_t)k * 65536 + t * 257];     // diagonal of to_queries[k]
    __syncthreads();
    const float* tr = tk + (size_t)k * 65536 + (size_t)t * D_;   // to_keys[k][e=t][:]
    #pragma unroll
    for (int h = 0; h < H_; h++) {
        const float4* r4 = (const float4*)(tr + h * 64);
        const float4* q4 = (const float4*)(q_sh + h * 64);
        float a = 0.0f;
        #pragma unroll
        for (int j = 0; j < 16; j++) {
            float4 rv = r4[j], qv = q4[j];
            a += rv.x*qv.x + rv.y*qv.y + rv.z*qv.z + rv.w*qv.w;
        }
        g_w[((size_t)b * D_ + t) * 32 + k * 4 + h] = SCALEF * a;
    }
}

// ------------------- fused: dots + softmax(k) + head-avg + attn_vis + rowsum + agg -------------------
// grid (16 token-tiles, 16 batches), 256 threads. Tile = 128 tokens, subtiles of 32.
__global__ __launch_bounds__(256) void k_attn(float* __restrict__ vis) {
    __shared__ __align__(16) float w_sh[D_ * 32];     // [e][k*4+h], 32 KB
    __shared__ float dots_sh[32][33];
    __shared__ float att_sh[32][8];
    int tid = threadIdx.x, lane = tid & 31, wid = tid >> 5;
    int b = blockIdx.y;
    int n0 = blockIdx.x * 128;
    const float* wsrc = g_w + (size_t)b * (D_ * 32);
    for (int i = tid; i < 2048; i += 256)
        ((float4*)w_sh)[i] = ((const float4*)wsrc)[i];
    __syncthreads();

    float acc8[8];
    #pragma unroll
    for (int j = 0; j < 8; j++) acc8[j] = 0.0f;
    float rs = 0.0f;

    for (int s = 0; s < 4; s++) {
        int nb = n0 + s * 32;
        // ---- dots: warp computes 4 tokens x 32 (k,h); lane = k*4+h ----
        float acc[4] = {0.0f, 0.0f, 0.0f, 0.0f};
        const float* eb = g_emb + ((size_t)(b * N_ + nb + (wid << 2))) * D_;
        #pragma unroll 4
        for (int e = 0; e < D_; e += 4) {
            float w0 = w_sh[(e+0)*32 + lane], w1 = w_sh[(e+1)*32 + lane];
            float w2 = w_sh[(e+2)*32 + lane], w3 = w_sh[(e+3)*32 + lane];
            #pragma unroll
            for (int t = 0; t < 4; t++) {
                float4 ev = *(const float4*)(eb + t * D_ + e);
                acc[t] += ev.x*w0 + ev.y*w1 + ev.z*w2 + ev.w*w3;
            }
        }
        #pragma unroll
        for (int t = 0; t < 4; t++) dots_sh[(wid << 2) + t][lane] = acc[t];
        __syncthreads();
        // ---- softmax over k per (token,h); head-average into att_sh ----
        if (tid < 128) {
            int t = tid >> 2, h = tid & 3;
            float d[8], mx = -1e30f;
            #pragma unroll
            for (int k = 0; k < 8; k++) { d[k] = dots_sh[t][k*4 + h]; mx = fmaxf(mx, d[k]); }
            float sm = 0.0f;
            #pragma unroll
            for (int k = 0; k < 8; k++) { d[k] = __expf(d[k] - mx); sm += d[k]; }
            float inv = 1.0f / sm;
            #pragma unroll
            for (int k = 0; k < 8; k++) {
                float v = d[k] * inv;
                v += __shfl_xor_sync(0xffffffffu, v, 1);
                v += __shfl_xor_sync(0xffffffffu, v, 2);
                if (h == 0) att_sh[t][k] = v * 0.25f;
            }
        }
        __syncthreads();
        // ---- attn_vis ----
        {
            int t = tid >> 3, k = tid & 7;
            vis[((size_t)b * K_ + k) * N_ + nb + t] = att_sh[t][k];
        }
        // ---- agg: warp 'wid' = slot k; lane owns 8 e-values ----
        const float* e2 = g_emb + ((size_t)(b * N_ + nb)) * D_ + lane * 8;
        #pragma unroll 4
        for (int t = 0; t < 32; t++) {
            float a = att_sh[t][wid];
            float4 u  = *(const float4*)(e2 + t * D_);
            float4 v2 = *(const float4*)(e2 + t * D_ + 4);
            acc8[0] += a*u.x;  acc8[1] += a*u.y;  acc8[2] += a*u.z;  acc8[3] += a*u.w;
            acc8[4] += a*v2.x; acc8[5] += a*v2.y; acc8[6] += a*v2.z; acc8[7] += a*v2.w;
            rs += a;
        }
        __syncthreads();
    }
    float* ap = g_aggp + (((size_t)(b * 16 + blockIdx.x)) * K_ + wid) * D_ + lane * 8;
    *(float4*)ap       = make_float4(acc8[0], acc8[1], acc8[2], acc8[3]);
    *(float4*)(ap + 4) = make_float4(acc8[4], acc8[5], acc8[6], acc8[7]);
    if (lane == 0) g_rsp[((size_t)b * 16 + blockIdx.x) * K_ + wid] = rs;
}

// ------------------- upd[b,k,:] = (agg @ to_values[k]) / rowsum -------------------
__global__ __launch_bounds__(256) void k_upd(const float* __restrict__ tv) {
    __shared__ float agg_sh[D_];
    __shared__ float inv_sh;
    int bk = blockIdx.x, b = bk >> 3, k = bk & 7, t = threadIdx.x;
    float a = 0.0f;
    #pragma unroll
    for (int tile = 0; tile < 16; tile++)
        a += g_aggp[(((size_t)(b * 16 + tile)) * K_ + k) * D_ + t];
    agg_sh[t] = a;
    if (t == 0) {
        float r = 0.0f;
        #pragma unroll
        for (int tile = 0; tile < 16; tile++) r += g_rsp[((size_t)b * 16 + tile) * K_ + k];
        inv_sh = 1.0f / r;
    }
    __syncthreads();
    const float* tvk = tv + (size_t)k * 65536 + t;
    float acc = 0.0f;
    #pragma unroll 8
    for (int e = 0; e < D_; e++) acc += agg_sh[e] * __ldg(tvk + e * D_);
    g_upd[(size_t)bk * D_ + t] = acc * inv_sh;
}

// ------------------- generic small SGEMM: C = act(A @ B^T + bias [+ C]) -------------------
// M=128 fixed (grid.y*32). A/C chosen device-side (no symbol-address API needed).
__device__ __forceinline__ const float* gemmA(int s) {
    return s == 0 ? g_upd : s == 1 ? g_slots : s == 2 ? g_pre : g_hid;
}
__device__ __forceinline__ float* gemmC(int s) {
    return s == 0 ? g_gi : s == 1 ? g_gh : s == 2 ? g_hid : g_slots;
}
__global__ __launch_bounds__(256) void k_gemm(const float* __restrict__ Bm,
                                              const float* __restrict__ bias,
                                              int Asel, int Csel,
                                              int N, int Kd, int relu, int acc) {
    __shared__ float As[32][33];
    __shared__ float Bs[64][33];
    const float* A = gemmA(Asel);
    float* C = gemmC(Csel);
    int tid = threadIdx.x;
    int m0 = blockIdx.y * 32, n0 = blockIdx.x * 64;
    int tx = tid & 31, ty = tid >> 5;
    float av[4][2] = {{0,0},{0,0},{0,0},{0,0}};
    for (int k0 = 0; k0 < Kd; k0 += 32) {
        #pragma unroll
        for (int r = 0; r < 4; r++) {
            int i = tid + r * 256;
            As[i >> 5][i & 31] = A[(size_t)(m0 + (i >> 5)) * Kd + k0 + (i & 31)];
        }
        #pragma unroll
        for (int r = 0; r < 8; r++) {
            int i = tid + r * 256;
            Bs[i >> 5][i & 31] = Bm[(size_t)(n0 + (i >> 5)) * Kd + k0 + (i & 31)];
        }
        __syncthreads();
        #pragma unroll
        for (int k = 0; k < 32; k++) {
            float b0 = Bs[tx * 2][k], b1 = Bs[tx * 2 + 1][k];
            #pragma unroll
            for (int i = 0; i < 4; i++) {
                float a = As[ty * 4 + i][k];
                av[i][0] += a * b0;
                av[i][1] += a * b1;
            }
        }
        __syncthreads();
    }
    #pragma unroll
    for (int i = 0; i < 4; i++)
        #pragma unroll
        for (int j = 0; j < 2; j++) {
            int m = m0 + ty * 4 + i, n = n0 + tx * 2 + j;
            float v = av[i][j] + bias[n];
            if (relu) v = fmaxf(v, 0.0f);
            if (acc) v += C[(size_t)m * N + n];
            C[(size_t)m * N + n] = v;
        }
}

// ------------------- GRU gates -------------------
__global__ void k_gates() {
    int i = blockIdx.x * 256 + threadIdx.x;     // 0..32767
    int row = i >> 8, d = i & 255;
    const float* gi = g_gi + (size_t)row * 768;
    const float* gh = g_gh + (size_t)row * 768;
    float ir = gi[d], iz = gi[256 + d], in_ = gi[512 + d];
    float hr = gh[d], hz = gh[256 + d], hn  = gh[512 + d];
    float r = 1.0f / (1.0f + __expf(-(ir + hr)));
    float z = 1.0f / (1.0f + __expf(-(iz + hz)));
    float n = tanhf(in_ + r * hn);
    float h = g_slots[i];
    g_slots[i] = (1.0f - z) * n + z * h;
}

__global__ void k_copy(float* __restrict__ out) {
    int i = blockIdx.x * 256 + threadIdx.x;
    out[i] = g_slots[i];
}

// ------------------- launch -------------------
extern "C" void kernel_launch(void* const* d_in, const int* in_sizes, int n_in,
                              void* d_out, int out_size) {
    const float* emb   = (const float*)d_in[0];
    const float* noise = (const float*)d_in[1];
    const float* mu    = (const float*)d_in[2];
    const float* ls    = (const float*)d_in[3];
    const float* tk    = (const float*)d_in[4];
    const float* tq    = (const float*)d_in[5];
    const float* tv    = (const float*)d_in[6];
    const float* w_ih  = (const float*)d_in[7];
    const float* w_hh  = (const float*)d_in[8];
    const float* b_ih  = (const float*)d_in[9];
    const float* b_hh  = (const float*)d_in[10];
    const float* w1    = (const float*)d_in[11];
    const float* b1    = (const float*)d_in[12];
    const float* w2    = (const float*)d_in[13];
    const float* b2    = (const float*)d_in[14];
    const float* ln_in_g = (const float*)d_in[15];
    const float* ln_in_b = (const float*)d_in[16];
    const float* ln_sl_g = (const float*)d_in[17];
    const float* ln_sl_b = (const float*)d_in[18];
    const float* ln_ff_g = (const float*)d_in[19];
    const float* ln_ff_b = (const float*)d_in[20];

    float* out = (float*)d_out;
    float* vis = out + B_ * K_ * D_;            // slots first, then attn_vis

    k_init_slots<<<128, 256>>>(mu, ls, noise);
    k_lnrow<<<B_ * N_ / 8, 256>>>(emb, ln_in_g, ln_in_b, 0);

    for (int it = 0; it < 3; it++) {
        k_w<<<128, 256>>>(tq, tk, ln_sl_g, ln_sl_b);
        k_attn<<<dim3(16, 16), 256>>>(vis);
        k_upd<<<128, 256>>>(tv);
        k_gemm<<<dim3(12, 4), 256>>>(w_ih, b_ih, /*A*/0, /*C*/0, 768, 256, 0, 0);   // gi
        k_gemm<<<dim3(12, 4), 256>>>(w_hh, b_hh, /*A*/1, /*C*/1, 768, 256, 0, 0);   // gh
        k_gates<<<128, 256>>>();
        k_lnrow<<<16, 256>>>(nullptr, ln_ff_g, ln_ff_b, 1);
        k_gemm<<<dim3(16, 4), 256>>>(w1, b1, /*A*/2, /*C*/2, 1024, 256, 1, 0);      // mlp1 + relu
        k_gemm<<<dim3(4, 4), 256>>>(w2, b2, /*A*/3, /*C*/3, 256, 1024, 0, 1);       // mlp2, accumulate
    }
    k_copy<<<128, 256>>>(out);
}

// round 3
// speedup vs baseline: 1.0293x; 1.0293x over previous
#include <cuda_runtime.h>
#include <math.h>

#define B_ 16
#define N_ 2048
#define D_ 256
#define K_ 8
#define H_ 4
#define HID_ 1024
#define LN_EPS 1e-5f
#define SCALEF 0.0625f   // 256^-0.5
#define NT_ 64           // token tiles (N_/32)

// ------------------- static device scratch (no allocations) -------------------
static __device__ float g_emb  [B_*N_*D_];        // LayerNorm'd embeddings (33.5 MB, L2-resident)
static __device__ float g_slots[B_*K_*D_];
static __device__ float g_w    [B_*D_*K_*H_];     // folded key*query weights, [b][e][k*4+h]
static __device__ float g_aggp [B_*NT_*K_*D_];    // per-token-tile partial attn@emb (8 MB)
static __device__ float g_rsp  [B_*NT_*K_];       // per-token-tile partial rowsums
static __device__ float g_upd  [B_*K_*D_];
static __device__ float g_gi   [B_*K_*3*D_];
static __device__ float g_gh   [B_*K_*3*D_];
static __device__ float g_pre  [B_*K_*D_];
static __device__ float g_hid  [B_*K_*HID_];

// ------------------- slots = mu + exp(logsigma)*noise -------------------
__global__ void k_init_slots(const float* __restrict__ mu, const float* __restrict__ ls,
                             const float* __restrict__ nz) {
    int i = blockIdx.x * 256 + threadIdx.x;          // 32768
    int kd = i & (K_*D_ - 1);
    g_slots[i] = mu[kd] + __expf(ls[kd]) * nz[i];
}

// ------------------- row LayerNorm (one warp per 256-wide row) -------------------
// mode 0: x=xin -> g_emb ; mode 1: x=g_slots -> g_pre
__global__ __launch_bounds__(256) void k_lnrow(const float* __restrict__ xin,
                                               const float* __restrict__ g,
                                               const float* __restrict__ b, int mode) {
    int wid = threadIdx.x >> 5, lane = threadIdx.x & 31;
    size_t row = (size_t)blockIdx.x * 8 + wid;
    const float* x  = (mode == 0) ? xin : g_slots;
    float*       out = (mode == 0) ? g_emb : g_pre;
    const float* xr = x + row * D_;
    float4 v0 = ((const float4*)xr)[lane];
    float4 v1 = ((const float4*)xr)[32 + lane];
    float s = v0.x+v0.y+v0.z+v0.w + v1.x+v1.y+v1.z+v1.w;
    float q = v0.x*v0.x+v0.y*v0.y+v0.z*v0.z+v0.w*v0.w
            + v1.x*v1.x+v1.y*v1.y+v1.z*v1.z+v1.w*v1.w;
    #pragma unroll
    for (int o = 16; o; o >>= 1) {
        s += __shfl_xor_sync(0xffffffffu, s, o);
        q += __shfl_xor_sync(0xffffffffu, q, o);
    }
    float m  = s * (1.0f / D_);
    float rs = rsqrtf(q * (1.0f / D_) - m * m + LN_EPS);
    float4 g0 = ((const float4*)g)[lane],      b0 = ((const float4*)b)[lane];
    float4 g1 = ((const float4*)g)[32 + lane], b1 = ((const float4*)b)[32 + lane];
    float4 o0, o1;
    o0.x = (v0.x-m)*rs*g0.x + b0.x;  o0.y = (v0.y-m)*rs*g0.y + b0.y;
    o0.z = (v0.z-m)*rs*g0.z + b0.z;  o0.w = (v0.w-m)*rs*g0.w + b0.w;
    o1.x = (v1.x-m)*rs*g1.x + b1.x;  o1.y = (v1.y-m)*rs*g1.y + b1.y;
    o1.z = (v1.z-m)*rs*g1.z + b1.z;  o1.w = (v1.w-m)*rs*g1.w + b1.w;
    ((float4*)(out + row * D_))[lane]      = o0;
    ((float4*)(out + row * D_))[32 + lane] = o1;
}

// ------------------- per (b,k): LN(slots) -> q=diag(to_queries)*s -> w = SCALE*tk@q -------------------
__global__ __launch_bounds__(256) void k_w(const float* __restrict__ tq,
                                           const float* __restrict__ tk,
                                           const float* __restrict__ lg,
                                           const float* __restrict__ lb) {
    __shared__ float q_sh[D_];
    __shared__ float red[16];
    int bk = blockIdx.x, b = bk >> 3, k = bk & 7, t = threadIdx.x;
    float x = g_slots[(size_t)bk * D_ + t];
    float s = x, q = x * x;
    #pragma unroll
    for (int o = 16; o; o >>= 1) {
        s += __shfl_xor_sync(0xffffffffu, s, o);
        q += __shfl_xor_sync(0xffffffffu, q, o);
    }
    if ((t & 31) == 0) { red[t >> 5] = s; red[8 + (t >> 5)] = q; }
    __syncthreads();
    float S = 0.0f, Q = 0.0f;
    #pragma unroll
    for (int i = 0; i < 8; i++) { S += red[i]; Q += red[8 + i]; }
    float m  = S * (1.0f / D_);
    float rs = rsqrtf(Q * (1.0f / D_) - m * m + LN_EPS);
    float sv = (x - m) * rs * lg[t] + lb[t];
    q_sh[t] = sv * tq[(size_t)k * 65536 + t * 257];     // diagonal of to_queries[k]
    __syncthreads();
    const float* tr = tk + (size_t)k * 65536 + (size_t)t * D_;   // to_keys[k][e=t][:]
    #pragma unroll
    for (int h = 0; h < H_; h++) {
        const float4* r4 = (const float4*)(tr + h * 64);
        const float4* q4 = (const float4*)(q_sh + h * 64);
        float a = 0.0f;
        #pragma unroll
        for (int j = 0; j < 16; j++) {
            float4 rv = r4[j], qv = q4[j];
            a += rv.x*qv.x + rv.y*qv.y + rv.z*qv.z + rv.w*qv.w;
        }
        g_w[((size_t)b * D_ + t) * 32 + k * 4 + h] = SCALEF * a;
    }
}

// ------------------- fused: dots + softmax(k) + head-avg + attn_vis + rowsum + agg -------------------
// grid (64 token-tiles, 16 batches) = 1024 blocks, 256 threads, tile = 32 tokens.
__global__ __launch_bounds__(256, 5) void k_attn(float* __restrict__ vis) {
    __shared__ __align__(16) float w_sh[D_ * 32];     // [e][k*4+h], 32 KB
    __shared__ float dots_sh[32][33];
    __shared__ float att_sh[32][9];
    int tid = threadIdx.x, lane = tid & 31, wid = tid >> 5;
    int b = blockIdx.y;
    int nb = blockIdx.x * 32;
    const float* wsrc = g_w + (size_t)b * (D_ * 32);
    #pragma unroll
    for (int r = 0; r < 8; r++)
        ((float4*)w_sh)[tid + r * 256] = ((const float4*)wsrc)[tid + r * 256];
    __syncthreads();

    // ---- dots: warp computes 4 tokens x 32 (k,h); lane = k*4+h ----
    float acc[4] = {0.0f, 0.0f, 0.0f, 0.0f};
    const float* eb = g_emb + ((size_t)(b * N_ + nb + (wid << 2))) * D_;
    #pragma unroll 4
    for (int e = 0; e < D_; e += 4) {
        float w0 = w_sh[(e+0)*32 + lane], w1 = w_sh[(e+1)*32 + lane];
        float w2 = w_sh[(e+2)*32 + lane], w3 = w_sh[(e+3)*32 + lane];
        #pragma unroll
        for (int t = 0; t < 4; t++) {
            float4 ev = *(const float4*)(eb + t * D_ + e);
            acc[t] += ev.x*w0 + ev.y*w1 + ev.z*w2 + ev.w*w3;
        }
    }
    #pragma unroll
    for (int t = 0; t < 4; t++) dots_sh[(wid << 2) + t][lane] = acc[t];
    __syncthreads();

    // ---- softmax over k per (token,h); head-average into att_sh ----
    if (tid < 128) {
        int t = tid >> 2, h = tid & 3;
        float d[8], mx = -1e30f;
        #pragma unroll
        for (int k = 0; k < 8; k++) { d[k] = dots_sh[t][k*4 + h]; mx = fmaxf(mx, d[k]); }
        float sm = 0.0f;
        #pragma unroll
        for (int k = 0; k < 8; k++) { d[k] = __expf(d[k] - mx); sm += d[k]; }
        float inv = 1.0f / sm;
        #pragma unroll
        for (int k = 0; k < 8; k++) {
            float v = d[k] * inv;
            v += __shfl_xor_sync(0xffffffffu, v, 1);
            v += __shfl_xor_sync(0xffffffffu, v, 2);
            if (h == 0) att_sh[t][k] = v * 0.25f;
        }
    }
    __syncthreads();

    // ---- attn_vis: warp = slot, lane = token (coalesced 128B per warp) ----
    vis[((size_t)b * K_ + wid) * N_ + nb + lane] = att_sh[lane][wid];

    // ---- agg: warp 'wid' = slot k; lane owns 8 e-values ----
    float acc8[8] = {0,0,0,0,0,0,0,0};
    float rs = 0.0f;
    const float* e2 = g_emb + ((size_t)(b * N_ + nb)) * D_ + lane * 8;
    #pragma unroll 4
    for (int t = 0; t < 32; t++) {
        float a = att_sh[t][wid];
        float4 u  = *(const float4*)(e2 + t * D_);
        float4 v2 = *(const float4*)(e2 + t * D_ + 4);
        acc8[0] += a*u.x;  acc8[1] += a*u.y;  acc8[2] += a*u.z;  acc8[3] += a*u.w;
        acc8[4] += a*v2.x; acc8[5] += a*v2.y; acc8[6] += a*v2.z; acc8[7] += a*v2.w;
        rs += a;
    }
    float* ap = g_aggp + (((size_t)(b * NT_ + blockIdx.x)) * K_ + wid) * D_ + lane * 8;
    *(float4*)ap       = make_float4(acc8[0], acc8[1], acc8[2], acc8[3]);
    *(float4*)(ap + 4) = make_float4(acc8[4], acc8[5], acc8[6], acc8[7]);
    if (lane == 0) g_rsp[((size_t)b * NT_ + blockIdx.x) * K_ + wid] = rs;
}

// ------------------- upd[b,k,:] = (agg @ to_values[k]) / rowsum -------------------
__global__ __launch_bounds__(256) void k_upd(const float* __restrict__ tv) {
    __shared__ float agg_sh[D_];
    __shared__ float inv_sh;
    int bk = blockIdx.x, b = bk >> 3, k = bk & 7, t = threadIdx.x;
    float a = 0.0f;
    #pragma unroll 8
    for (int tile = 0; tile < NT_; tile++)
        a += g_aggp[(((size_t)(b * NT_ + tile)) * K_ + k) * D_ + t];
    agg_sh[t] = a;
    if (t == 0) {
        float r = 0.0f;
        #pragma unroll
        for (int tile = 0; tile < NT_; tile++) r += g_rsp[((size_t)b * NT_ + tile) * K_ + k];
        inv_sh = 1.0f / r;
    }
    __syncthreads();
    const float* tvk = tv + (size_t)k * 65536 + t;
    float acc = 0.0f;
    #pragma unroll 8
    for (int e = 0; e < D_; e++) acc += agg_sh[e] * __ldg(tvk + e * D_);
    g_upd[(size_t)bk * D_ + t] = acc * inv_sh;
}

// ------------------- generic small SGEMM: C = act(A @ B^T + bias [+ C]) -------------------
__device__ __forceinline__ const float* gemmA(int s) {
    return s == 0 ? g_upd : s == 1 ? g_slots : s == 2 ? g_pre : g_hid;
}
__device__ __forceinline__ float* gemmC(int s) {
    return s == 0 ? g_gi : s == 1 ? g_gh : s == 2 ? g_hid : g_slots;
}
__global__ __launch_bounds__(256) void k_gemm(const float* __restrict__ Bm,
                                              const float* __restrict__ bias,
                                              int Asel, int Csel,
                                              int N, int Kd, int relu, int acc) {
    __shared__ float As[32][33];
    __shared__ float Bs[64][33];
    const float* A = gemmA(Asel);
    float* C = gemmC(Csel);
    int tid = threadIdx.x;
    int m0 = blockIdx.y * 32, n0 = blockIdx.x * 64;
    int tx = tid & 31, ty = tid >> 5;
    float av[4][2] = {{0,0},{0,0},{0,0},{0,0}};
    for (int k0 = 0; k0 < Kd; k0 += 32) {
        #pragma unroll
        for (int r = 0; r < 4; r++) {
            int i = tid + r * 256;
            As[i >> 5][i & 31] = A[(size_t)(m0 + (i >> 5)) * Kd + k0 + (i & 31)];
        }
        #pragma unroll
        for (int r = 0; r < 8; r++) {
            int i = tid + r * 256;
            Bs[i >> 5][i & 31] = Bm[(size_t)(n0 + (i >> 5)) * Kd + k0 + (i & 31)];
        }
        __syncthreads();
        #pragma unroll
        for (int k = 0; k < 32; k++) {
            float b0 = Bs[tx * 2][k], b1 = Bs[tx * 2 + 1][k];
            #pragma unroll
            for (int i = 0; i < 4; i++) {
                float a = As[ty * 4 + i][k];
                av[i][0] += a * b0;
                av[i][1] += a * b1;
            }
        }
        __syncthreads();
    }
    #pragma unroll
    for (int i = 0; i < 4; i++)
        #pragma unroll
        for (int j = 0; j < 2; j++) {
            int m = m0 + ty * 4 + i, n = n0 + tx * 2 + j;
            float v = av[i][j] + bias[n];
            if (relu) v = fmaxf(v, 0.0f);
            if (acc) v += C[(size_t)m * N + n];
            C[(size_t)m * N + n] = v;
        }
}

// ------------------- GRU gates -------------------
__global__ void k_gates() {
    int i = blockIdx.x * 256 + threadIdx.x;     // 0..32767
    int row = i >> 8, d = i & 255;
    const float* gi = g_gi + (size_t)row * 768;
    const float* gh = g_gh + (size_t)row * 768;
    float ir = gi[d], iz = gi[256 + d], in_ = gi[512 + d];
    float hr = gh[d], hz = gh[256 + d], hn  = gh[512 + d];
    float r = 1.0f / (1.0f + __expf(-(ir + hr)));
    float z = 1.0f / (1.0f + __expf(-(iz + hz)));
    float n = tanhf(in_ + r * hn);
    float h = g_slots[i];
    g_slots[i] = (1.0f - z) * n + z * h;
}

__global__ void k_copy(float* __restrict__ out) {
    int i = blockIdx.x * 256 + threadIdx.x;
    out[i] = g_slots[i];
}

// ------------------- launch -------------------
extern "C" void kernel_launch(void* const* d_in, const int* in_sizes, int n_in,
                              void* d_out, int out_size) {
    const float* emb   = (const float*)d_in[0];
    const float* noise = (const float*)d_in[1];
    const float* mu    = (const float*)d_in[2];
    const float* ls    = (const float*)d_in[3];
    const float* tk    = (const float*)d_in[4];
    const float* tq    = (const float*)d_in[5];
    const float* tv    = (const float*)d_in[6];
    const float* w_ih  = (const float*)d_in[7];
    const float* w_hh  = (const float*)d_in[8];
    const float* b_ih  = (const float*)d_in[9];
    const float* b_hh  = (const float*)d_in[10];
    const float* w1    = (const float*)d_in[11];
    const float* b1    = (const float*)d_in[12];
    const float* w2    = (const float*)d_in[13];
    const float* b2    = (const float*)d_in[14];
    const float* ln_in_g = (const float*)d_in[15];
    const float* ln_in_b = (const float*)d_in[16];
    const float* ln_sl_g = (const float*)d_in[17];
    const float* ln_sl_b = (const float*)d_in[18];
    const float* ln_ff_g = (const float*)d_in[19];
    const float* ln_ff_b = (const float*)d_in[20];

    float* out = (float*)d_out;
    float* vis = out + B_ * K_ * D_;            // slots first, then attn_vis

    k_init_slots<<<128, 256>>>(mu, ls, noise);
    k_lnrow<<<B_ * N_ / 8, 256>>>(emb, ln_in_g, ln_in_b, 0);

    for (int it = 0; it < 3; it++) {
        k_w<<<128, 256>>>(tq, tk, ln_sl_g, ln_sl_b);
        k_attn<<<dim3(NT_, 16), 256>>>(vis);
        k_upd<<<128, 256>>>(tv);
        k_gemm<<<dim3(12, 4), 256>>>(w_ih, b_ih, /*A*/0, /*C*/0, 768, 256, 0, 0);   // gi
        k_gemm<<<dim3(12, 4), 256>>>(w_hh, b_hh, /*A*/1, /*C*/1, 768, 256, 0, 0);   // gh
        k_gates<<<128, 256>>>();
        k_lnrow<<<16, 256>>>(nullptr, ln_ff_g, ln_ff_b, 1);
        k_gemm<<<dim3(16, 4), 256>>>(w1, b1, /*A*/2, /*C*/2, 1024, 256, 1, 0);      // mlp1 + relu
        k_gemm<<<dim3(4, 4), 256>>>(w2, b2, /*A*/3, /*C*/3, 256, 1024, 0, 1);       // mlp2, accumulate
    }
    k_copy<<<128, 256>>>(out);
}

// round 4
// speedup vs baseline: 1.1726x; 1.1393x over previous
#include <cuda_runtime.h>
#include <math.h>

#define B_ 16
#define N_ 2048
#define D_ 256
#define K_ 8
#define H_ 4
#define HID_ 1024
#define LN_EPS 1e-5f
#define SCALEF 0.0625f   // 256^-0.5
#define NT_ 64           // token tiles (N_/32)
#define EST 264          // emb_sh row stride (floats)

// ------------------- static device scratch (no allocations) -------------------
static __device__ float g_emb  [B_*N_*D_];
static __device__ float g_slots[B_*K_*D_];
static __device__ float g_w    [B_*D_*K_*H_];
static __device__ float g_aggp [B_*NT_*K_*D_];
static __device__ float g_rsp  [B_*NT_*K_];
static __device__ float g_upd  [B_*K_*D_];
static __device__ float g_gi   [B_*K_*3*D_];
static __device__ float g_gh   [B_*K_*3*D_];
static __device__ float g_pre  [B_*K_*D_];
static __device__ float g_hid  [B_*K_*HID_];

__global__ void k_init_slots(const float* __restrict__ mu, const float* __restrict__ ls,
                             const float* __restrict__ nz) {
    int i = blockIdx.x * 256 + threadIdx.x;
    int kd = i & (K_*D_ - 1);
    g_slots[i] = mu[kd] + __expf(ls[kd]) * nz[i];
}

__global__ __launch_bounds__(256) void k_lnemb(const float* __restrict__ xin,
                                               const float* __restrict__ g,
                                               const float* __restrict__ b) {
    int wid = threadIdx.x >> 5, lane = threadIdx.x & 31;
    size_t row = (size_t)blockIdx.x * 8 + wid;
    const float* xr = xin + row * D_;
    float4 v0 = ((const float4*)xr)[lane];
    float4 v1 = ((const float4*)xr)[32 + lane];
    float s = v0.x+v0.y+v0.z+v0.w + v1.x+v1.y+v1.z+v1.w;
    float q = v0.x*v0.x+v0.y*v0.y+v0.z*v0.z+v0.w*v0.w
            + v1.x*v1.x+v1.y*v1.y+v1.z*v1.z+v1.w*v1.w;
    #pragma unroll
    for (int o = 16; o; o >>= 1) {
        s += __shfl_xor_sync(0xffffffffu, s, o);
        q += __shfl_xor_sync(0xffffffffu, q, o);
    }
    float m  = s * (1.0f / D_);
    float rs = rsqrtf(q * (1.0f / D_) - m * m + LN_EPS);
    float4 g0 = ((const float4*)g)[lane],      b0 = ((const float4*)b)[lane];
    float4 g1 = ((const float4*)g)[32 + lane], b1 = ((const float4*)b)[32 + lane];
    float4 o0, o1;
    o0.x = (v0.x-m)*rs*g0.x + b0.x;  o0.y = (v0.y-m)*rs*g0.y + b0.y;
    o0.z = (v0.z-m)*rs*g0.z + b0.z;  o0.w = (v0.w-m)*rs*g0.w + b0.w;
    o1.x = (v1.x-m)*rs*g1.x + b1.x;  o1.y = (v1.y-m)*rs*g1.y + b1.y;
    o1.z = (v1.z-m)*rs*g1.z + b1.z;  o1.w = (v1.w-m)*rs*g1.w + b1.w;
    ((float4*)(g_emb + row * D_))[lane]      = o0;
    ((float4*)(g_emb + row * D_))[32 + lane] = o1;
}

__global__ __launch_bounds__(256) void k_w(const float* __restrict__ tq,
                                           const float* __restrict__ tk,
                                           const float* __restrict__ lg,
                                           const float* __restrict__ lb) {
    __shared__ float q_sh[D_];
    __shared__ float red[16];
    int bk = blockIdx.x, b = bk >> 3, k = bk & 7, t = threadIdx.x;
    float x = g_slots[(size_t)bk * D_ + t];
    float s = x, q = x * x;
    #pragma unroll
    for (int o = 16; o; o >>= 1) {
        s += __shfl_xor_sync(0xffffffffu, s, o);
        q += __shfl_xor_sync(0xffffffffu, q, o);
    }
    if ((t & 31) == 0) { red[t >> 5] = s; red[8 + (t >> 5)] = q; }
    __syncthreads();
    float S = 0.0f, Q = 0.0f;
    #pragma unroll
    for (int i = 0; i < 8; i++) { S += red[i]; Q += red[8 + i]; }
    float m  = S * (1.0f / D_);
    float rs = rsqrtf(Q * (1.0f / D_) - m * m + LN_EPS);
    float sv = (x - m) * rs * lg[t] + lb[t];
    q_sh[t] = sv * tq[(size_t)k * 65536 + t * 257];
    __syncthreads();
    const float* tr = tk + (size_t)k * 65536 + (size_t)t * D_;
    #pragma unroll
    for (int h = 0; h < H_; h++) {
        const float4* r4 = (const float4*)(tr + h * 64);
        const float4* q4 = (const float4*)(q_sh + h * 64);
        float a = 0.0f;
        #pragma unroll
        for (int j = 0; j < 16; j++) {
            float4 rv = r4[j], qv = q4[j];
            a += rv.x*qv.x + rv.y*qv.y + rv.z*qv.z + rv.w*qv.w;
        }
        g_w[((size_t)b * D_ + t) * 32 + k * 4 + h] = SCALEF * a;
    }
}

// fused attention: emb tile staged in shared; dots + softmax + vis + agg all LDS-fed
__global__ __launch_bounds__(256) void k_attn(float* __restrict__ vis) {
    extern __shared__ __align__(16) float sm[];
    float* w_sh    = sm;                    // [e][kh]  8192 floats
    float* emb_sh  = sm + 8192;             // [t][e]   32*EST
    float* dots_sh = emb_sh + 32 * EST;     // [t][kh]  32*33
    float* att_sh  = dots_sh + 32 * 33;     // [t][k]   32*9

    int tid = threadIdx.x, lane = tid & 31, wid = tid >> 5;
    int b = blockIdx.y;
    int nb = blockIdx.x * 32;

    const float4* wsrc = (const float4*)(g_w + (size_t)b * (D_ * 32));
    #pragma unroll
    for (int r = 0; r < 8; r++)
        ((float4*)w_sh)[tid + r * 256] = wsrc[tid + r * 256];
    const float4* esrc = (const float4*)(g_emb + ((size_t)(b * N_ + nb)) * D_);
    #pragma unroll
    for (int r = 0; r < 8; r++) {
        int i = tid + r * 256;
        int row = i >> 6, c4 = i & 63;
        ((float4*)(emb_sh + row * EST))[c4] = esrc[(size_t)row * 64 + c4];
    }
    __syncthreads();

    float acc[4] = {0.0f, 0.0f, 0.0f, 0.0f};
    const float* er = emb_sh + (wid << 2) * EST;
    #pragma unroll 4
    for (int e = 0; e < D_; e += 4) {
        float w0 = w_sh[(e+0)*32 + lane], w1 = w_sh[(e+1)*32 + lane];
        float w2 = w_sh[(e+2)*32 + lane], w3 = w_sh[(e+3)*32 + lane];
        #pragma unroll
        for (int t = 0; t < 4; t++) {
            float4 ev = *(const float4*)(er + t * EST + e);
            acc[t] += ev.x*w0 + ev.y*w1 + ev.z*w2 + ev.w*w3;
        }
    }
    #pragma unroll
    for (int t = 0; t < 4; t++) dots_sh[((wid << 2) + t) * 33 + lane] = acc[t];
    __syncthreads();

    if (tid < 128) {
        int t = tid >> 2, h = tid & 3;
        float d[8], mx = -1e30f;
        #pragma unroll
        for (int k = 0; k < 8; k++) { d[k] = dots_sh[t * 33 + k*4 + h]; mx = fmaxf(mx, d[k]); }
        float smx = 0.0f;
        #pragma unroll
        for (int k = 0; k < 8; k++) { d[k] = __expf(d[k] - mx); smx += d[k]; }
        float inv = 1.0f / smx;
        #pragma unroll
        for (int k = 0; k < 8; k++) {
            float v = d[k] * inv;
            v += __shfl_xor_sync(0xffffffffu, v, 1);
            v += __shfl_xor_sync(0xffffffffu, v, 2);
            if (h == 0) att_sh[t * 9 + k] = v * 0.25f;
        }
    }
    __syncthreads();

    vis[((size_t)b * K_ + wid) * N_ + nb + lane] = att_sh[lane * 9 + wid];

    float acc8[8] = {0,0,0,0,0,0,0,0};
    float rs = 0.0f;
    const float* e2 = emb_sh + lane * 8;
    #pragma unroll 4
    for (int t = 0; t < 32; t++) {
        float a = att_sh[t * 9 + wid];
        float4 u  = *(const float4*)(e2 + t * EST);
        float4 v2 = *(const float4*)(e2 + t * EST + 4);
        acc8[0] += a*u.x;  acc8[1] += a*u.y;  acc8[2] += a*u.z;  acc8[3] += a*u.w;
        acc8[4] += a*v2.x; acc8[5] += a*v2.y; acc8[6] += a*v2.z; acc8[7] += a*v2.w;
        rs += a;
    }
    float* ap = g_aggp + (((size_t)(b * NT_ + blockIdx.x)) * K_ + wid) * D_ + lane * 8;
    *(float4*)ap       = make_float4(acc8[0], acc8[1], acc8[2], acc8[3]);
    *(float4*)(ap + 4) = make_float4(acc8[4], acc8[5], acc8[6], acc8[7]);
    if (lane == 0) g_rsp[((size_t)b * NT_ + blockIdx.x) * K_ + wid] = rs;
}

__global__ __launch_bounds__(256) void k_upd(const float* __restrict__ tv) {
    __shared__ float agg_sh[D_];
    __shared__ float inv_sh;
    int bk = blockIdx.x, b = bk >> 3, k = bk & 7, t = threadIdx.x;
    float a = 0.0f;
    #pragma unroll 8
    for (int tile = 0; tile < NT_; tile++)
        a += g_aggp[(((size_t)(b * NT_ + tile)) * K_ + k) * D_ + t];
    agg_sh[t] = a;
    if (t == 0) {
        float r = 0.0f;
        #pragma unroll
        for (int tile = 0; tile < NT_; tile++) r += g_rsp[((size_t)b * NT_ + tile) * K_ + k];
        inv_sh = 1.0f / r;
    }
    __syncthreads();
    const float* tvk = tv + (size_t)k * 65536 + t;
    float acc = 0.0f;
    #pragma unroll 8
    for (int e = 0; e < D_; e++) acc += agg_sh[e] * __ldg(tvk + e * D_);
    g_upd[(size_t)bk * D_ + t] = acc * inv_sh;
}

__device__ __forceinline__ void gemm_body(const float* __restrict__ A,
                                          const float* __restrict__ Bm,
                                          const float* __restrict__ bias,
                                          float* __restrict__ C,
                                          int N, int Kd, int relu, int acc,
                                          int m0, int n0, float* __restrict__ outp) {
    __shared__ float As[32][33];
    __shared__ float Bs[64][33];
    int tid = threadIdx.x;
    int tx = tid & 31, ty = tid >> 5;
    float av[4][2] = {{0,0},{0,0},{0,0},{0,0}};
    for (int k0 = 0; k0 < Kd; k0 += 32) {
        #pragma unroll
        for (int r = 0; r < 4; r++) {
            int i = tid + r * 256;
            As[i >> 5][i & 31] = A[(size_t)(m0 + (i >> 5)) * Kd + k0 + (i & 31)];
        }
        #pragma unroll
        for (int r = 0; r < 8; r++) {
            int i = tid + r * 256;
            Bs[i >> 5][i & 31] = Bm[(size_t)(n0 + (i >> 5)) * Kd + k0 + (i & 31)];
        }
        __syncthreads();
        #pragma unroll
        for (int k = 0; k < 32; k++) {
            float b0 = Bs[tx * 2][k], b1 = Bs[tx * 2 + 1][k];
            #pragma unroll
            for (int i = 0; i < 4; i++) {
                float a = As[ty * 4 + i][k];
                av[i][0] += a * b0;
                av[i][1] += a * b1;
            }
        }
        __syncthreads();
    }
    #pragma unroll
    for (int i = 0; i < 4; i++)
        #pragma unroll
        for (int j = 0; j < 2; j++) {
            int m = m0 + ty * 4 + i, n = n0 + tx * 2 + j;
            float v = av[i][j] + bias[n];
            if (relu) v = fmaxf(v, 0.0f);
            if (acc) v += C[(size_t)m * N + n];
            C[(size_t)m * N + n] = v;
            if (outp) outp[(size_t)m * N + n] = v;
        }
}

__global__ __launch_bounds__(256) void k_mlp1(const float* __restrict__ w1,
                                              const float* __restrict__ b1) {
    gemm_body(g_pre, w1, b1, g_hid, HID_, D_, 1, 0, blockIdx.y * 32, blockIdx.x * 64, nullptr);
}
__global__ __launch_bounds__(256) void k_mlp2(const float* __restrict__ w2,
                                              const float* __restrict__ b2,
                                              float* __restrict__ outp) {
    gemm_body(g_hid, w2, b2, g_slots, D_, HID_, 0, 1, blockIdx.y * 32, blockIdx.x * 64, outp);
}
__global__ __launch_bounds__(256) void k_gru(const float* __restrict__ wih,
                                             const float* __restrict__ whh,
                                             const float* __restrict__ bih,
                                             const float* __restrict__ bhh) {
    if (blockIdx.x < 12)
        gemm_body(g_upd, wih, bih, g_gi, 768, D_, 0, 0, blockIdx.y * 32, blockIdx.x * 64, nullptr);
    else
        gemm_body(g_slots, whh, bhh, g_gh, 768, D_, 0, 0, blockIdx.y * 32, (blockIdx.x - 12) * 64, nullptr);
}

__global__ __launch_bounds__(256) void k_gates_ln(const float* __restrict__ lg,
                                                  const float* __restrict__ lb) {
    __shared__ float red[16];
    int row = blockIdx.x, t = threadIdx.x;
    const float* gi = g_gi + (size_t)row * 768;
    const float* gh = g_gh + (size_t)row * 768;
    float ir = gi[t], iz = gi[256 + t], in_ = gi[512 + t];
    float hr = gh[t], hz = gh[256 + t], hn  = gh[512 + t];
    float r = 1.0f / (1.0f + __expf(-(ir + hr)));
    float z = 1.0f / (1.0f + __expf(-(iz + hz)));
    float n = tanhf(in_ + r * hn);
    float h = g_slots[(size_t)row * D_ + t];
    float s = (1.0f - z) * n + z * h;
    g_slots[(size_t)row * D_ + t] = s;
    float a = s, q = s * s;
    #pragma unroll
    for (int o = 16; o; o >>= 1) {
        a += __shfl_xor_sync(0xffffffffu, a, o);
        q += __shfl_xor_sync(0xffffffffu, q, o);
    }
    if ((t & 31) == 0) { red[t >> 5] = a; red[8 + (t >> 5)] = q; }
    __syncthreads();
    float S = 0.0f, Q = 0.0f;
    #pragma unroll
    for (int i = 0; i < 8; i++) { S += red[i]; Q += red[8 + i]; }
    float m  = S * (1.0f / D_);
    float rs = rsqrtf(Q * (1.0f / D_) - m * m + LN_EPS);
    g_pre[(size_t)row * D_ + t] = (s - m) * rs * lg[t] + lb[t];
}

extern "C" void kernel_launch(void* const* d_in, const int* in_sizes, int n_in,
                              void* d_out, int out_size) {
    const float* emb   = (const float*)d_in[0];
    const float* noise = (const float*)d_in[1];
    const float* mu    = (const float*)d_in[2];
    const float* ls    = (const float*)d_in[3];
    const float* tk    = (const float*)d_in[4];
    const float* tq    = (const float*)d_in[5];
    const float* tv    = (const float*)d_in[6];
    const float* w_ih  = (const float*)d_in[7];
    const float* w_hh  = (const float*)d_in[8];
    const float* b_ih  = (const float*)d_in[9];
    const float* b_hh  = (const float*)d_in[10];
    const float* w1    = (const float*)d_in[11];
    const float* b1    = (const float*)d_in[12];
    const float* w2    = (const float*)d_in[13];
    const float* b2    = (const float*)d_in[14];
    const float* ln_in_g = (const float*)d_in[15];
    const float* ln_in_b = (const float*)d_in[16];
    const float* ln_sl_g = (const float*)d_in[17];
    const float* ln_sl_b = (const float*)d_in[18];
    const float* ln_ff_g = (const float*)d_in[19];
    const float* ln_ff_b = (const float*)d_in[20];

    float* out = (float*)d_out;
    float* vis = out + B_ * K_ * D_;

    const int ATTN_SMEM = (8192 + 32 * EST + 32 * 33 + 32 * 9) * 4;
    cudaFuncSetAttribute(k_attn, cudaFuncAttributeMaxDynamicSharedMemorySize, ATTN_SMEM);

    k_init_slots<<<128, 256>>>(mu, ls, noise);
    k_lnemb<<<B_ * N_ / 8, 256>>>(emb, ln_in_g, ln_in_b);

    for (int it = 0; it < 3; it++) {
        k_w<<<128, 256>>>(tq, tk, ln_sl_g, ln_sl_b);
        k_attn<<<dim3(NT_, 16), 256, ATTN_SMEM>>>(vis);
        k_upd<<<128, 256>>>(tv);
        k_gru<<<dim3(24, 4), 256>>>(w_ih, w_hh, b_ih, b_hh);
        k_gates_ln<<<128, 256>>>(ln_ff_g, ln_ff_b);
        k_mlp1<<<dim3(16, 4), 256>>>(w1, b1);
        k_mlp2<<<dim3(4, 4), 256>>>(w2, b2, (it == 2) ? out : nullptr);
    }
}

// round 5
// speedup vs baseline: 1.8222x; 1.5539x over previous
#include <cuda_runtime.h>
#include <math.h>

#define B_ 16
#define N_ 2048
#define D_ 256
#define K_ 8
#define H_ 4
#define HID_ 1024
#define LN_EPS 1e-5f
#define SCALEF 0.0625f   // 256^-0.5
#define NT_ 64           // token tiles (N_/32)
#define EST 264          // emb_sh row stride (floats, 16B-aligned, broadcast reads)
#define WST 260          // w_sh row stride (floats, 16B-aligned, conflict-free LDS.128)
#define NB_ 128          // mega-kernel block count (single wave, <= 148 SMs)

// packed f32x2 FMA: acc.lo += a.lo*b.lo ; acc.hi += a.hi*b.hi
#define FMA2(acc, a, b) \
    asm("fma.rn.f32x2 %0, %1, %2, %0;" : "+l"(acc) : "l"(a), "l"(b))
#define DUP2(dst, f) \
    asm("mov.b64 %0, {%1, %1};" : "=l"(dst) : "f"(f))
#define UNPK2(lo, hi, v) \
    asm("mov.b64 {%0, %1}, %2;" : "=f"(lo), "=f"(hi) : "l"(v))

// ------------------- static device scratch (no allocations) -------------------
static __device__ float g_emb  [B_*N_*D_];        // LN'd embeddings (L2-resident)
static __device__ float g_slots[B_*K_*D_];
static __device__ float g_w    [B_*K_*H_*D_];     // folded weights, layout [b][kh][e]
static __device__ float g_aggp [B_*NT_*K_*D_];    // per-tile partial attn@emb
static __device__ float g_rsp  [B_*NT_*K_];
static __device__ float g_upd  [B_*K_*D_];
static __device__ float g_gi   [B_*K_*3*D_];
static __device__ float g_gh   [B_*K_*3*D_];
static __device__ float g_pre  [B_*K_*D_];
static __device__ float g_hid  [B_*K_*HID_];
static __device__ float g_m2p  [4*B_*K_*D_];      // mlp2 split-K partials

// device barrier state (generation barrier; returns to steady state each launch)
static __device__ unsigned          g_cnt = 0;
static __device__ volatile unsigned g_gen = 0;

__device__ __forceinline__ void gsync() {
    __syncthreads();
    if (threadIdx.x == 0) {
        __threadfence();
        unsigned gen = g_gen;
        if (atomicAdd(&g_cnt, 1) == NB_ - 1) {
            g_cnt = 0;
            __threadfence();
            g_gen = gen + 1;
        } else {
            while (g_gen == gen) { }
        }
        __threadfence();
    }
    __syncthreads();
}

// ------------------- slots = mu + exp(logsigma)*noise -------------------
__global__ void k_init_slots(const float* __restrict__ mu, const float* __restrict__ ls,
                             const float* __restrict__ nz) {
    int i = blockIdx.x * 256 + threadIdx.x;
    int kd = i & (K_*D_ - 1);
    g_slots[i] = mu[kd] + __expf(ls[kd]) * nz[i];
}

// ------------------- embeddings LayerNorm (one warp per row) -------------------
__global__ __launch_bounds__(256) void k_lnemb(const float* __restrict__ xin,
                                               const float* __restrict__ g,
                                               const float* __restrict__ b) {
    int wid = threadIdx.x >> 5, lane = threadIdx.x & 31;
    size_t row = (size_t)blockIdx.x * 8 + wid;
    const float* xr = xin + row * D_;
    float4 v0 = ((const float4*)xr)[lane];
    float4 v1 = ((const float4*)xr)[32 + lane];
    float s = v0.x+v0.y+v0.z+v0.w + v1.x+v1.y+v1.z+v1.w;
    float q = v0.x*v0.x+v0.y*v0.y+v0.z*v0.z+v0.w*v0.w
            + v1.x*v1.x+v1.y*v1.y+v1.z*v1.z+v1.w*v1.w;
    #pragma unroll
    for (int o = 16; o; o >>= 1) {
        s += __shfl_xor_sync(0xffffffffu, s, o);
        q += __shfl_xor_sync(0xffffffffu, q, o);
    }
    float m  = s * (1.0f / D_);
    float rs = rsqrtf(q * (1.0f / D_) - m * m + LN_EPS);
    float4 g0 = ((const float4*)g)[lane],      b0 = ((const float4*)b)[lane];
    float4 g1 = ((const float4*)g)[32 + lane], b1 = ((const float4*)b)[32 + lane];
    float4 o0, o1;
    o0.x = (v0.x-m)*rs*g0.x + b0.x;  o0.y = (v0.y-m)*rs*g0.y + b0.y;
    o0.z = (v0.z-m)*rs*g0.z + b0.z;  o0.w = (v0.w-m)*rs*g0.w + b0.w;
    o1.x = (v1.x-m)*rs*g1.x + b1.x;  o1.y = (v1.y-m)*rs*g1.y + b1.y;
    o1.z = (v1.z-m)*rs*g1.z + b1.z;  o1.w = (v1.w-m)*rs*g1.w + b1.w;
    ((float4*)(g_emb + row * D_))[lane]      = o0;
    ((float4*)(g_emb + row * D_))[32 + lane] = o1;
}

// ------------------- shared body: LN(slot row) -> q -> w (writes g_w [b][kh][e]) ----
__device__ __forceinline__ void w_body(float x, int b, int k, int t,
                                       const float* __restrict__ tq,
                                       const float* __restrict__ tk,
                                       const float* __restrict__ lg,
                                       const float* __restrict__ lb,
                                       float* q_sh, float* red) {
    float s = x, q = x * x;
    #pragma unroll
    for (int o = 16; o; o >>= 1) {
        s += __shfl_xor_sync(0xffffffffu, s, o);
        q += __shfl_xor_sync(0xffffffffu, q, o);
    }
    if ((t & 31) == 0) { red[t >> 5] = s; red[8 + (t >> 5)] = q; }
    __syncthreads();
    float S = 0.0f, Q = 0.0f;
    #pragma unroll
    for (int i = 0; i < 8; i++) { S += red[i]; Q += red[8 + i]; }
    float m  = S * (1.0f / D_);
    float rs = rsqrtf(Q * (1.0f / D_) - m * m + LN_EPS);
    float sv = (x - m) * rs * lg[t] + lb[t];
    q_sh[t] = sv * tq[(size_t)k * 65536 + t * 257];      // diag of to_queries[k]
    __syncthreads();
    const float* tr = tk + (size_t)k * 65536 + (size_t)t * D_;
    #pragma unroll
    for (int h = 0; h < H_; h++) {
        const float4* r4 = (const float4*)(tr + h * 64);
        const float4* q4 = (const float4*)(q_sh + h * 64);
        float a = 0.0f;
        #pragma unroll
        for (int j = 0; j < 16; j++) {
            float4 rv = r4[j], qv = q4[j];
            a += rv.x*qv.x + rv.y*qv.y + rv.z*qv.z + rv.w*qv.w;
        }
        g_w[((size_t)(b * 32 + k * 4 + h)) * D_ + t] = SCALEF * a;
    }
}

// standalone w-kernel for the first iteration
__global__ __launch_bounds__(256) void k_w0(const float* __restrict__ tq,
                                            const float* __restrict__ tk,
                                            const float* __restrict__ lg,
                                            const float* __restrict__ lb) {
    __shared__ float q_sh[D_];
    __shared__ float red[16];
    int bk = blockIdx.x, b = bk >> 3, k = bk & 7, t = threadIdx.x;
    w_body(g_slots[(size_t)bk * D_ + t], b, k, t, tq, tk, lg, lb, q_sh, red);
}

// ------------------- fused attention (f32x2 packed math, all-LDS inner loops) ----
__global__ __launch_bounds__(256) void k_attn(float* __restrict__ vis, int wvis) {
    extern __shared__ __align__(16) float sm[];
    float* w_sh    = sm;                    // [kh][e] stride WST : 32*260
    float* emb_sh  = w_sh + 32 * WST;       // [t][e]  stride EST : 32*264
    float* dots_sh = emb_sh + 32 * EST;     // [t][kh] stride 33
    float* att_sh  = dots_sh + 32 * 33;     // [t][k]  stride 9

    int tid = threadIdx.x, lane = tid & 31, wid = tid >> 5;
    int b = blockIdx.y;
    int nb = blockIdx.x * 32;

    // fill w (transposed layout from g_w [b][kh][e]) and emb tile, coalesced
    const float4* wsrc = (const float4*)(g_w + (size_t)b * 8192);
    #pragma unroll
    for (int r = 0; r < 8; r++) {
        int j = tid + r * 256;                 // 2048 float4: kh = j>>6, e4 = j&63
        *(float4*)(w_sh + (j >> 6) * WST + (j & 63) * 4) = wsrc[j];
    }
    const float4* esrc = (const float4*)(g_emb + ((size_t)(b * N_ + nb)) * D_);
    #pragma unroll
    for (int r = 0; r < 8; r++) {
        int j = tid + r * 256;
        *(float4*)(emb_sh + (j >> 6) * EST + (j & 63) * 4) = esrc[j];
    }
    __syncthreads();

    // ---- dots: warp = 4 tokens, lane = kh; packed f32x2 ----
    unsigned long long acc2[4] = {0ull, 0ull, 0ull, 0ull};
    const float* er = emb_sh + (wid << 2) * EST;
    const float* wr = w_sh + lane * WST;
    #pragma unroll 4
    for (int e = 0; e < D_; e += 4) {
        ulonglong2 wv = *(const ulonglong2*)(wr + e);          // LDS.128 conflict-free
        #pragma unroll
        for (int t = 0; t < 4; t++) {
            ulonglong2 ev = *(const ulonglong2*)(er + t * EST + e);  // broadcast LDS.128
            FMA2(acc2[t], ev.x, wv.x);
            FMA2(acc2[t], ev.y, wv.y);
        }
    }
    #pragma unroll
    for (int t = 0; t < 4; t++) {
        float lo, hi; UNPK2(lo, hi, acc2[t]);
        dots_sh[((wid << 2) + t) * 33 + lane] = lo + hi;
    }
    __syncthreads();

    // ---- softmax over k per (token,h); head-average ----
    if (tid < 128) {
        int t = tid >> 2, h = tid & 3;
        float d[8], mx = -1e30f;
        #pragma unroll
        for (int k = 0; k < 8; k++) { d[k] = dots_sh[t * 33 + k*4 + h]; mx = fmaxf(mx, d[k]); }
        float smx = 0.0f;
        #pragma unroll
        for (int k = 0; k < 8; k++) { d[k] = __expf(d[k] - mx); smx += d[k]; }
        float inv = 1.0f / smx;
        #pragma unroll
        for (int k = 0; k < 8; k++) {
            float v = d[k] * inv;
            v += __shfl_xor_sync(0xffffffffu, v, 1);
            v += __shfl_xor_sync(0xffffffffu, v, 2);
            if (h == 0) att_sh[t * 9 + k] = v * 0.25f;
        }
    }
    __syncthreads();

    // ---- attn_vis (only on last iteration) ----
    if (wvis)
        vis[((size_t)b * K_ + wid) * N_ + nb + lane] = att_sh[lane * 9 + wid];

    // ---- agg: warp = slot k; lane owns e=4*lane and 128+4*lane; packed f32x2 ----
    unsigned long long a0 = 0ull, a1 = 0ull, a2 = 0ull, a3 = 0ull;
    float rs = 0.0f;
    const float* e2 = emb_sh + lane * 4;
    #pragma unroll 4
    for (int t = 0; t < 32; t++) {
        float a = att_sh[t * 9 + wid];
        unsigned long long aa; DUP2(aa, a);
        ulonglong2 u = *(const ulonglong2*)(e2 + t * EST);           // LDS.128 conflict-free
        ulonglong2 v = *(const ulonglong2*)(e2 + t * EST + 128);
        FMA2(a0, u.x, aa);  FMA2(a1, u.y, aa);
        FMA2(a2, v.x, aa);  FMA2(a3, v.y, aa);
        rs += a;
    }
    float f0, f1, f2, f3, f4, f5, f6, f7;
    UNPK2(f0, f1, a0);  UNPK2(f2, f3, a1);
    UNPK2(f4, f5, a2);  UNPK2(f6, f7, a3);
    float* ap = g_aggp + (((size_t)(b * NT_ + blockIdx.x)) * K_ + wid) * D_;
    *(float4*)(ap + lane * 4)       = make_float4(f0, f1, f2, f3);
    *(float4*)(ap + 128 + lane * 4) = make_float4(f4, f5, f6, f7);
    if (lane == 0) g_rsp[((size_t)b * NT_ + blockIdx.x) * K_ + wid] = rs;
}

// ------------------- tiled GEMM phase body (32x64 tile, K-range) -------------------
__device__ __forceinline__ void gemm_phase(const float* __restrict__ A,
                                           const float* __restrict__ Bm,
                                           float* pool,
                                           int Kstride, int k0b, int k0e,
                                           int m0, int n0, int N,
                                           float* __restrict__ C,
                                           const float* __restrict__ bias, int relu) {
    float* As = pool;            // [32][33]
    float* Bs = pool + 32 * 33;  // [64][33]
    int tid = threadIdx.x;
    int tx = tid & 31, ty = tid >> 5;
    float av[4][2] = {{0,0},{0,0},{0,0},{0,0}};
    for (int k0 = k0b; k0 < k0e; k0 += 32) {
        #pragma unroll
        for (int r = 0; r < 4; r++) {
            int i = tid + r * 256;
            As[(i >> 5) * 33 + (i & 31)] = A[(size_t)(m0 + (i >> 5)) * Kstride + k0 + (i & 31)];
        }
        #pragma unroll
        for (int r = 0; r < 8; r++) {
            int i = tid + r * 256;
            Bs[(i >> 5) * 33 + (i & 31)] = Bm[(size_t)(n0 + (i >> 5)) * Kstride + k0 + (i & 31)];
        }
        __syncthreads();
        #pragma unroll
        for (int k = 0; k < 32; k++) {
            float b0 = Bs[(tx * 2) * 33 + k], b1 = Bs[(tx * 2 + 1) * 33 + k];
            #pragma unroll
            for (int i = 0; i < 4; i++) {
                float a = As[(ty * 4 + i) * 33 + k];
                av[i][0] += a * b0;
                av[i][1] += a * b1;
            }
        }
        __syncthreads();
    }
    #pragma unroll
    for (int i = 0; i < 4; i++)
        #pragma unroll
        for (int j = 0; j < 2; j++) {
            int m = m0 + ty * 4 + i, n = n0 + tx * 2 + j;
            float v = av[i][j];
            if (bias) v += bias[n];
            if (relu) v = fmaxf(v, 0.0f);
            C[(size_t)m * N + n] = v;
        }
}

// ------------------- persistent mega-kernel: upd -> GRU -> gates+LN -> MLP -> fin+w ----
__global__ __launch_bounds__(256) void k_mega(
    const float* __restrict__ tq, const float* __restrict__ tk, const float* __restrict__ tv,
    const float* __restrict__ wih, const float* __restrict__ whh,
    const float* __restrict__ bih, const float* __restrict__ bhh,
    const float* __restrict__ w1, const float* __restrict__ b1,
    const float* __restrict__ w2, const float* __restrict__ b2,
    const float* __restrict__ ln_sl_g, const float* __restrict__ ln_sl_b,
    const float* __restrict__ ln_ff_g, const float* __restrict__ ln_ff_b,
    int last, float* __restrict__ out)
{
    __shared__ float pool[32 * 33 + 64 * 33];     // max phase smem (12.7 KB)
    int bid = blockIdx.x, tid = threadIdx.x;

    // ---- P0: upd[b,k,:] = (Σ_tiles aggp) @ to_values[k] / rowsum ----
    {
        float* agg_sh = pool;
        int b = bid >> 3, k = bid & 7;
        float a = 0.0f;
        #pragma unroll 8
        for (int tile = 0; tile < NT_; tile++)
            a += g_aggp[(((size_t)(b * NT_ + tile)) * K_ + k) * D_ + tid];
        agg_sh[tid] = a;
        if (tid == 0) {
            float r = 0.0f;
            #pragma unroll
            for (int tile = 0; tile < NT_; tile++)
                r += g_rsp[((size_t)b * NT_ + tile) * K_ + k];
            pool[256] = 1.0f / r;
        }
        __syncthreads();
        const float* tvk = tv + (size_t)k * 65536 + tid;
        float acc = 0.0f;
        #pragma unroll 8
        for (int e = 0; e < D_; e++) acc += agg_sh[e] * __ldg(tvk + e * D_);
        float inv = pool[256];
        __syncthreads();
        g_upd[(size_t)bid * D_ + tid] = acc * inv;
    }
    gsync();

    // ---- P1: GRU pre-activations gi = upd@wih^T+bih, gh = slots@whh^T+bhh ----
    if (bid < 96) {
        int x = bid % 24, y = bid / 24;
        if (x < 12)
            gemm_phase(g_upd, wih, pool, D_, 0, D_, y * 32, x * 64, 768, g_gi, bih, 0);
        else
            gemm_phase(g_slots, whh, pool, D_, 0, D_, y * 32, (x - 12) * 64, 768, g_gh, bhh, 0);
    }
    gsync();

    // ---- P2: GRU gates + pre-MLP LayerNorm(ln_ff) -> g_slots, g_pre ----
    {
        float* red = pool;
        int row = bid, t = tid;
        const float* gi = g_gi + (size_t)row * 768;
        const float* gh = g_gh + (size_t)row * 768;
        float ir = gi[t], iz = gi[256 + t], in_ = gi[512 + t];
        float hr = gh[t], hz = gh[256 + t], hn  = gh[512 + t];
        float r = 1.0f / (1.0f + __expf(-(ir + hr)));
        float z = 1.0f / (1.0f + __expf(-(iz + hz)));
        float n = tanhf(in_ + r * hn);
        float h = g_slots[(size_t)row * D_ + t];
        float s = (1.0f - z) * n + z * h;
        g_slots[(size_t)row * D_ + t] = s;
        float a = s, q = s * s;
        #pragma unroll
        for (int o = 16; o; o >>= 1) {
            a += __shfl_xor_sync(0xffffffffu, a, o);
            q += __shfl_xor_sync(0xffffffffu, q, o);
        }
        if ((t & 31) == 0) { red[t >> 5] = a; red[8 + (t >> 5)] = q; }
        __syncthreads();
        float S = 0.0f, Q = 0.0f;
        #pragma unroll
        for (int i = 0; i < 8; i++) { S += red[i]; Q += red[8 + i]; }
        float m  = S * (1.0f / D_);
        float rs = rsqrtf(Q * (1.0f / D_) - m * m + LN_EPS);
        g_pre[(size_t)row * D_ + t] = (s - m) * rs * ln_ff_g[t] + ln_ff_b[t];
    }
    gsync();

    // ---- P3: mlp1 = relu(pre @ w1^T + b1) ----
    if (bid < 64)
        gemm_phase(g_pre, w1, pool, D_, 0, D_, (bid >> 4) * 32, (bid & 15) * 64, HID_, g_hid, b1, 1);
    gsync();

    // ---- P4: mlp2 split-K partials (no bias) ----
    if (bid < 64) {
        int s = bid >> 4, rem = bid & 15;
        gemm_phase(g_hid, w2, pool, HID_, s * 256, s * 256 + 256,
                   (rem >> 2) * 32, (rem & 3) * 64, D_,
                   g_m2p + (size_t)s * (128 * D_), nullptr, 0);
    }
    gsync();

    // ---- P5: reduce partials + bias + residual -> slots ; then next-iter w (or output) ----
    {
        int row = bid, b = row >> 3, k = row & 7, t = tid;
        float v = g_slots[(size_t)row * D_ + t] + b2[t];
        #pragma unroll
        for (int s = 0; s < 4; s++)
            v += g_m2p[(size_t)s * (128 * D_) + (size_t)row * D_ + t];
        g_slots[(size_t)row * D_ + t] = v;
        if (last) {
            out[(size_t)row * D_ + t] = v;
        } else {
            float* q_sh = pool;
            float* red  = pool + 256;
            w_body(v, b, k, t, tq, tk, ln_sl_g, ln_sl_b, q_sh, red);
        }
    }
}

// ------------------- launch -------------------
extern "C" void kernel_launch(void* const* d_in, const int* in_sizes, int n_in,
                              void* d_out, int out_size) {
    const float* emb   = (const float*)d_in[0];
    const float* noise = (const float*)d_in[1];
    const float* mu    = (const float*)d_in[2];
    const float* ls    = (const float*)d_in[3];
    const float* tk    = (const float*)d_in[4];
    const float* tq    = (const float*)d_in[5];
    const float* tv    = (const float*)d_in[6];
    const float* w_ih  = (const float*)d_in[7];
    const float* w_hh  = (const float*)d_in[8];
    const float* b_ih  = (const float*)d_in[9];
    const float* b_hh  = (const float*)d_in[10];
    const float* w1    = (const float*)d_in[11];
    const float* b1    = (const float*)d_in[12];
    const float* w2    = (const float*)d_in[13];
    const float* b2    = (const float*)d_in[14];
    const float* ln_in_g = (const float*)d_in[15];
    const float* ln_in_b = (const float*)d_in[16];
    const float* ln_sl_g = (const float*)d_in[17];
    const float* ln_sl_b = (const float*)d_in[18];
    const float* ln_ff_g = (const float*)d_in[19];
    const float* ln_ff_b = (const float*)d_in[20];

    float* out = (float*)d_out;
    float* vis = out + B_ * K_ * D_;            // slots first, then attn_vis

    const int ATTN_SMEM = (32 * WST + 32 * EST + 32 * 33 + 32 * 9) * 4;   // ~72.5 KB
    cudaFuncSetAttribute(k_attn, cudaFuncAttributeMaxDynamicSharedMemorySize, ATTN_SMEM);

    k_init_slots<<<128, 256>>>(mu, ls, noise);
    k_lnemb<<<B_ * N_ / 8, 256>>>(emb, ln_in_g, ln_in_b);
    k_w0<<<128, 256>>>(tq, tk, ln_sl_g, ln_sl_b);

    for (int it = 0; it < 3; it++) {
        k_attn<<<dim3(NT_, 16), 256, ATTN_SMEM>>>(vis, it == 2 ? 1 : 0);
        k_mega<<<NB_, 256>>>(tq, tk, tv, w_ih, w_hh, b_ih, b_hh,
                             w1, b1, w2, b2, ln_sl_g, ln_sl_b, ln_ff_g, ln_ff_b,
                             it == 2 ? 1 : 0, out);
    }
}

// round 6
// speedup vs baseline: 1.9171x; 1.0521x over previous
#include <cuda_runtime.h>
#include <math.h>

#define B_ 16
#define N_ 2048
#define D_ 256
#define K_ 8
#define H_ 4
#define HID_ 1024
#define LN_EPS 1e-5f
#define SCALEF 0.0625f   // 256^-0.5
#define NT_ 64           // token tiles (N_/32)
#define EST 264          // emb_sh row stride
#define WST 260          // w_sh row stride
#define NB2_ 256         // mega-kernel blocks (2/SM co-resident, <= 296)

// packed f32x2 FMA helpers
#define FMA2(acc, a, b) \
    asm("fma.rn.f32x2 %0, %1, %2, %0;" : "+l"(acc) : "l"(a), "l"(b))
#define DUP2(dst, f) \
    asm("mov.b64 %0, {%1, %1};" : "=l"(dst) : "f"(f))
#define UNPK2(lo, hi, v) \
    asm("mov.b64 {%0, %1}, %2;" : "=f"(lo), "=f"(hi) : "l"(v))

// ------------------- static device scratch (no allocations) -------------------
static __device__ float g_emb  [B_*N_*D_];
static __device__ float g_slots[B_*K_*D_];
static __device__ float g_w    [B_*K_*H_*D_];     // folded weights [b][kh][e]
static __device__ float g_aggp [B_*NT_*K_*D_];
static __device__ float g_rsp  [B_*NT_*K_];
static __device__ float g_updp [2*B_*K_*D_];      // upd partials (e-halves, inv applied)
static __device__ float g_gi   [B_*K_*3*D_];
static __device__ float g_gh   [B_*K_*3*D_];
static __device__ float g_pre  [B_*K_*D_];
static __device__ float g_hid  [B_*K_*HID_];
static __device__ float g_m2p  [8*B_*K_*D_];      // mlp2 split-K partials

// device barrier state
static __device__ unsigned          g_cnt = 0;
static __device__ volatile unsigned g_gen = 0;

__device__ __forceinline__ void gsync() {
    __syncthreads();
    if (threadIdx.x == 0) {
        __threadfence();
        unsigned gen = g_gen;
        if (atomicAdd(&g_cnt, 1) == NB2_ - 1) {
            g_cnt = 0;
            __threadfence();
            g_gen = gen + 1;
        } else {
            while (g_gen == gen) { }
        }
        __threadfence();
    }
    __syncthreads();
}

// ------------------- slots = mu + exp(logsigma)*noise -------------------
__global__ void k_init_slots(const float* __restrict__ mu, const float* __restrict__ ls,
                             const float* __restrict__ nz) {
    int i = blockIdx.x * 256 + threadIdx.x;
    int kd = i & (K_*D_ - 1);
    g_slots[i] = mu[kd] + __expf(ls[kd]) * nz[i];
}

// ------------------- embeddings LayerNorm (one warp per row) -------------------
__global__ __launch_bounds__(256) void k_lnemb(const float* __restrict__ xin,
                                               const float* __restrict__ g,
                                               const float* __restrict__ b) {
    int wid = threadIdx.x >> 5, lane = threadIdx.x & 31;
    size_t row = (size_t)blockIdx.x * 8 + wid;
    const float* xr = xin + row * D_;
    float4 v0 = ((const float4*)xr)[lane];
    float4 v1 = ((const float4*)xr)[32 + lane];
    float s = v0.x+v0.y+v0.z+v0.w + v1.x+v1.y+v1.z+v1.w;
    float q = v0.x*v0.x+v0.y*v0.y+v0.z*v0.z+v0.w*v0.w
            + v1.x*v1.x+v1.y*v1.y+v1.z*v1.z+v1.w*v1.w;
    #pragma unroll
    for (int o = 16; o; o >>= 1) {
        s += __shfl_xor_sync(0xffffffffu, s, o);
        q += __shfl_xor_sync(0xffffffffu, q, o);
    }
    float m  = s * (1.0f / D_);
    float rs = rsqrtf(q * (1.0f / D_) - m * m + LN_EPS);
    float4 g0 = ((const float4*)g)[lane],      b0 = ((const float4*)b)[lane];
    float4 g1 = ((const float4*)g)[32 + lane], b1 = ((const float4*)b)[32 + lane];
    float4 o0, o1;
    o0.x = (v0.x-m)*rs*g0.x + b0.x;  o0.y = (v0.y-m)*rs*g0.y + b0.y;
    o0.z = (v0.z-m)*rs*g0.z + b0.z;  o0.w = (v0.w-m)*rs*g0.w + b0.w;
    o1.x = (v1.x-m)*rs*g1.x + b1.x;  o1.y = (v1.y-m)*rs*g1.y + b1.y;
    o1.z = (v1.z-m)*rs*g1.z + b1.z;  o1.w = (v1.w-m)*rs*g1.w + b1.w;
    ((float4*)(g_emb + row * D_))[lane]      = o0;
    ((float4*)(g_emb + row * D_))[32 + lane] = o1;
}

// ------------------- standalone first-iteration w-fold (full row per block) ----
__global__ __launch_bounds__(256) void k_w0(const float* __restrict__ tq,
                                            const float* __restrict__ tk,
                                            const float* __restrict__ lg,
                                            const float* __restrict__ lb) {
    __shared__ float q_sh[D_];
    __shared__ float red[16];
    int bk = blockIdx.x, b = bk >> 3, k = bk & 7, t = threadIdx.x;
    float x = g_slots[(size_t)bk * D_ + t];
    float s = x, q = x * x;
    #pragma unroll
    for (int o = 16; o; o >>= 1) {
        s += __shfl_xor_sync(0xffffffffu, s, o);
        q += __shfl_xor_sync(0xffffffffu, q, o);
    }
    if ((t & 31) == 0) { red[t >> 5] = s; red[8 + (t >> 5)] = q; }
    __syncthreads();
    float S = 0.0f, Q = 0.0f;
    #pragma unroll
    for (int i = 0; i < 8; i++) { S += red[i]; Q += red[8 + i]; }
    float m  = S * (1.0f / D_);
    float rs = rsqrtf(Q * (1.0f / D_) - m * m + LN_EPS);
    float sv = (x - m) * rs * lg[t] + lb[t];
    q_sh[t] = sv * tq[(size_t)k * 65536 + t * 257];
    __syncthreads();
    const float* tr = tk + (size_t)k * 65536 + (size_t)t * D_;
    #pragma unroll
    for (int h = 0; h < H_; h++) {
        const float4* r4 = (const float4*)(tr + h * 64);
        const float4* q4 = (const float4*)(q_sh + h * 64);
        float a = 0.0f;
        #pragma unroll
        for (int j = 0; j < 16; j++) {
            float4 rv = r4[j], qv = q4[j];
            a += rv.x*qv.x + rv.y*qv.y + rv.z*qv.z + rv.w*qv.w;
        }
        g_w[((size_t)(b * 32 + k * 4 + h)) * D_ + t] = SCALEF * a;
    }
}

// ------------------- fused attention (unchanged from R5) -------------------
__global__ __launch_bounds__(256) void k_attn(float* __restrict__ vis, int wvis) {
    extern __shared__ __align__(16) float sm[];
    float* w_sh    = sm;
    float* emb_sh  = w_sh + 32 * WST;
    float* dots_sh = emb_sh + 32 * EST;
    float* att_sh  = dots_sh + 32 * 33;

    int tid = threadIdx.x, lane = tid & 31, wid = tid >> 5;
    int b = blockIdx.y;
    int nb = blockIdx.x * 32;

    const float4* wsrc = (const float4*)(g_w + (size_t)b * 8192);
    #pragma unroll
    for (int r = 0; r < 8; r++) {
        int j = tid + r * 256;
        *(float4*)(w_sh + (j >> 6) * WST + (j & 63) * 4) = wsrc[j];
    }
    const float4* esrc = (const float4*)(g_emb + ((size_t)(b * N_ + nb)) * D_);
    #pragma unroll
    for (int r = 0; r < 8; r++) {
        int j = tid + r * 256;
        *(float4*)(emb_sh + (j >> 6) * EST + (j & 63) * 4) = esrc[j];
    }
    __syncthreads();

    unsigned long long acc2[4] = {0ull, 0ull, 0ull, 0ull};
    const float* er = emb_sh + (wid << 2) * EST;
    const float* wr = w_sh + lane * WST;
    #pragma unroll 4
    for (int e = 0; e < D_; e += 4) {
        ulonglong2 wv = *(const ulonglong2*)(wr + e);
        #pragma unroll
        for (int t = 0; t < 4; t++) {
            ulonglong2 ev = *(const ulonglong2*)(er + t * EST + e);
            FMA2(acc2[t], ev.x, wv.x);
            FMA2(acc2[t], ev.y, wv.y);
        }
    }
    #pragma unroll
    for (int t = 0; t < 4; t++) {
        float lo, hi; UNPK2(lo, hi, acc2[t]);
        dots_sh[((wid << 2) + t) * 33 + lane] = lo + hi;
    }
    __syncthreads();

    if (tid < 128) {
        int t = tid >> 2, h = tid & 3;
        float d[8], mx = -1e30f;
        #pragma unroll
        for (int k = 0; k < 8; k++) { d[k] = dots_sh[t * 33 + k*4 + h]; mx = fmaxf(mx, d[k]); }
        float smx = 0.0f;
        #pragma unroll
        for (int k = 0; k < 8; k++) { d[k] = __expf(d[k] - mx); smx += d[k]; }
        float inv = 1.0f / smx;
        #pragma unroll
        for (int k = 0; k < 8; k++) {
            float v = d[k] * inv;
            v += __shfl_xor_sync(0xffffffffu, v, 1);
            v += __shfl_xor_sync(0xffffffffu, v, 2);
            if (h == 0) att_sh[t * 9 + k] = v * 0.25f;
        }
    }
    __syncthreads();

    if (wvis)
        vis[((size_t)b * K_ + wid) * N_ + nb + lane] = att_sh[lane * 9 + wid];

    unsigned long long a0 = 0ull, a1 = 0ull, a2 = 0ull, a3 = 0ull;
    float rs = 0.0f;
    const float* e2 = emb_sh + lane * 4;
    #pragma unroll 4
    for (int t = 0; t < 32; t++) {
        float a = att_sh[t * 9 + wid];
        unsigned long long aa; DUP2(aa, a);
        ulonglong2 u = *(const ulonglong2*)(e2 + t * EST);
        ulonglong2 v = *(const ulonglong2*)(e2 + t * EST + 128);
        FMA2(a0, u.x, aa);  FMA2(a1, u.y, aa);
        FMA2(a2, v.x, aa);  FMA2(a3, v.y, aa);
        rs += a;
    }
    float f0, f1, f2, f3, f4, f5, f6, f7;
    UNPK2(f0, f1, a0);  UNPK2(f2, f3, a1);
    UNPK2(f4, f5, a2);  UNPK2(f6, f7, a3);
    float* ap = g_aggp + (((size_t)(b * NT_ + blockIdx.x)) * K_ + wid) * D_;
    *(float4*)(ap + lane * 4)       = make_float4(f0, f1, f2, f3);
    *(float4*)(ap + 128 + lane * 4) = make_float4(f4, f5, f6, f7);
    if (lane == 0) g_rsp[((size_t)b * NT_ + blockIdx.x) * K_ + wid] = rs;
}

// ------------------- persistent mega-kernel (256 blocks x 256 threads) -------------------
__global__ __launch_bounds__(256, 2) void k_mega(
    const float* __restrict__ tq, const float* __restrict__ tk, const float* __restrict__ tv,
    const float* __restrict__ wih, const float* __restrict__ whh,
    const float* __restrict__ bih, const float* __restrict__ bhh,
    const float* __restrict__ w1, const float* __restrict__ b1,
    const float* __restrict__ w2, const float* __restrict__ b2,
    const float* __restrict__ ln_sl_g, const float* __restrict__ ln_sl_b,
    const float* __restrict__ ln_ff_g, const float* __restrict__ ln_ff_b,
    int last, float* __restrict__ out)
{
    __shared__ float pool[2112];
    int bid = blockIdx.x, tid = threadIdx.x;

    // ---- P0: upd partials. block = (row, e-half). ----
    {
        int row = bid >> 1, half = bid & 1, b = row >> 3, k = row & 7;
        int e0 = half * 128;
        // tile-sum for my 128-e half, split tiles across thread halves
        float acc = 0.0f;
        int e = e0 + (tid & 127);
        int tb = (tid < 128) ? 0 : 32;
        const float* base = g_aggp + ((size_t)(b * NT_) * K_ + k) * D_ + e;
        #pragma unroll 8
        for (int tile = 0; tile < 32; tile++)
            acc += base[(size_t)(tb + tile) * (K_ * D_)];
        pool[tid] = acc;
        if (tid == 0) {
            float r = 0.0f;
            #pragma unroll
            for (int tile = 0; tile < NT_; tile++)
                r += g_rsp[((size_t)b * NT_ + tile) * K_ + k];
            pool[2048] = 1.0f / r;
        }
        __syncthreads();
        // matvec over my e-half, all 256 outputs, scaled by inv
        const float* tvk = tv + (size_t)k * 65536 + (size_t)e0 * D_ + tid;
        float mv = 0.0f;
        #pragma unroll 8
        for (int e2 = 0; e2 < 128; e2++)
            mv += (pool[e2] + pool[128 + e2]) * __ldg(tvk + (size_t)e2 * D_);
        g_updp[(size_t)half * 32768 + (size_t)row * D_ + tid] = mv * pool[2048];
    }
    gsync();

    // ---- P1: GRU pre-activations, 32x32 tiles (gi: 96 blocks, gh: 96 blocks) ----
    if (bid < 192) {
        int gsel = (bid >= 96) ? 1 : 0;
        int t2 = gsel ? bid - 96 : bid;
        int m0 = (t2 / 24) * 32, n0 = (t2 % 24) * 32;
        float* As = pool; float* Bs = pool + 32 * 33;
        const float* Bm  = gsel ? whh : wih;
        const float* bia = gsel ? bhh : bih;
        float* C = gsel ? g_gh : g_gi;
        int tx = tid & 15, ty = tid >> 4;
        float c00 = 0, c01 = 0, c10 = 0, c11 = 0;
        for (int k0 = 0; k0 < D_; k0 += 32) {
            #pragma unroll
            for (int r = 0; r < 4; r++) {
                int i = tid + r * 256;
                int m = m0 + (i >> 5), d = k0 + (i & 31);
                float av;
                if (gsel) av = g_slots[(size_t)m * D_ + d];
                else av = g_updp[(size_t)m * D_ + d] + g_updp[32768 + (size_t)m * D_ + d];
                As[(i >> 5) * 33 + (i & 31)] = av;
                Bs[(i >> 5) * 33 + (i & 31)] = Bm[(size_t)(n0 + (i >> 5)) * D_ + d];
            }
            __syncthreads();
            #pragma unroll
            for (int k = 0; k < 32; k++) {
                float a0 = As[(ty*2)*33 + k], a1 = As[(ty*2+1)*33 + k];
                float b0 = Bs[(tx*2)*33 + k], b1 = Bs[(tx*2+1)*33 + k];
                c00 += a0*b0; c01 += a0*b1; c10 += a1*b0; c11 += a1*b1;
            }
            __syncthreads();
        }
        int m = m0 + ty*2, n = n0 + tx*2;
        C[(size_t)m * 768 + n]       = c00 + bia[n];
        C[(size_t)m * 768 + n+1]     = c01 + bia[n+1];
        C[(size_t)(m+1) * 768 + n]   = c10 + bia[n];
        C[(size_t)(m+1) * 768 + n+1] = c11 + bia[n+1];
    }
    gsync();

    // ---- P2: GRU gates + pre-MLP LayerNorm(ff) -> g_slots, g_pre (128 blocks) ----
    if (bid < 128) {
        float* red = pool;
        int row = bid, t = tid;
        const float* gi = g_gi + (size_t)row * 768;
        const float* gh = g_gh + (size_t)row * 768;
        float ir = gi[t], iz = gi[256 + t], in_ = gi[512 + t];
        float hr = gh[t], hz = gh[256 + t], hn  = gh[512 + t];
        float r = 1.0f / (1.0f + __expf(-(ir + hr)));
        float z = 1.0f / (1.0f + __expf(-(iz + hz)));
        float n = tanhf(in_ + r * hn);
        float h = g_slots[(size_t)row * D_ + t];
        float s = (1.0f - z) * n + z * h;
        g_slots[(size_t)row * D_ + t] = s;
        float a = s, q = s * s;
        #pragma unroll
        for (int o = 16; o; o >>= 1) {
            a += __shfl_xor_sync(0xffffffffu, a, o);
            q += __shfl_xor_sync(0xffffffffu, q, o);
        }
        if ((t & 31) == 0) { red[t >> 5] = a; red[8 + (t >> 5)] = q; }
        __syncthreads();
        float S = 0.0f, Q = 0.0f;
        #pragma unroll
        for (int i = 0; i < 8; i++) { S += red[i]; Q += red[8 + i]; }
        float m  = S * (1.0f / D_);
        float rs = rsqrtf(Q * (1.0f / D_) - m * m + LN_EPS);
        g_pre[(size_t)row * D_ + t] = (s - m) * rs * ln_ff_g[t] + ln_ff_b[t];
    }
    gsync();

    // ---- P3: mlp1 = relu(pre @ w1^T + b1), 16x32 tiles, 256 blocks ----
    {
        int m0 = (bid >> 5) * 16, n0 = (bid & 31) * 32;
        float* As = pool; float* Bs = pool + 16 * 33;
        int tx = tid & 15, ty = tid >> 4;
        float c0 = 0, c1 = 0;
        for (int k0 = 0; k0 < D_; k0 += 32) {
            #pragma unroll
            for (int r = 0; r < 2; r++) {
                int i = tid + r * 256;
                As[(i >> 5) * 33 + (i & 31)] = g_pre[(size_t)(m0 + (i >> 5)) * D_ + k0 + (i & 31)];
            }
            #pragma unroll
            for (int r = 0; r < 4; r++) {
                int i = tid + r * 256;
                Bs[(i >> 5) * 33 + (i & 31)] = w1[(size_t)(n0 + (i >> 5)) * D_ + k0 + (i & 31)];
            }
            __syncthreads();
            #pragma unroll
            for (int k = 0; k < 32; k++) {
                float a = As[ty * 33 + k];
                c0 += a * Bs[(tx*2)*33 + k];
                c1 += a * Bs[(tx*2+1)*33 + k];
            }
            __syncthreads();
        }
        int m = m0 + ty, n = n0 + tx*2;
        g_hid[(size_t)m * HID_ + n]   = fmaxf(c0 + b1[n], 0.0f);
        g_hid[(size_t)m * HID_ + n+1] = fmaxf(c1 + b1[n+1], 0.0f);
    }
    gsync();

    // ---- P4: mlp2 split-K x8, 32x32 tiles, 256 blocks ----
    {
        int s = bid >> 5, t4 = bid & 31;
        int m0 = (t4 >> 3) * 32, n0 = (t4 & 7) * 32;
        float* As = pool; float* Bs = pool + 32 * 33;
        int tx = tid & 15, ty = tid >> 4;
        float c00 = 0, c01 = 0, c10 = 0, c11 = 0;
        for (int k0 = s * 128; k0 < s * 128 + 128; k0 += 32) {
            #pragma unroll
            for (int r = 0; r < 4; r++) {
                int i = tid + r * 256;
                As[(i >> 5) * 33 + (i & 31)] = g_hid[(size_t)(m0 + (i >> 5)) * HID_ + k0 + (i & 31)];
                Bs[(i >> 5) * 33 + (i & 31)] = w2[(size_t)(n0 + (i >> 5)) * HID_ + k0 + (i & 31)];
            }
            __syncthreads();
            #pragma unroll
            for (int k = 0; k < 32; k++) {
                float a0 = As[(ty*2)*33 + k], a1 = As[(ty*2+1)*33 + k];
                float b0 = Bs[(tx*2)*33 + k], b1 = Bs[(tx*2+1)*33 + k];
                c00 += a0*b0; c01 += a0*b1; c10 += a1*b0; c11 += a1*b1;
            }
            __syncthreads();
        }
        float* P = g_m2p + (size_t)s * 32768;
        int m = m0 + ty*2, n = n0 + tx*2;
        P[(size_t)m * D_ + n]       = c00;  P[(size_t)m * D_ + n+1]     = c01;
        P[(size_t)(m+1) * D_ + n]   = c10;  P[(size_t)(m+1) * D_ + n+1] = c11;
    }
    gsync();

    // ---- P5: reduce partials + bias + residual -> slots (+output on last) ----
    if (bid < 128) {
        int row = bid, t = tid;
        float v = g_slots[(size_t)row * D_ + t] + b2[t];
        #pragma unroll
        for (int s = 0; s < 8; s++)
            v += g_m2p[(size_t)s * 32768 + (size_t)row * D_ + t];
        g_slots[(size_t)row * D_ + t] = v;
        if (last) out[(size_t)row * D_ + t] = v;
    }

    // ---- P6: next-iteration w-fold, block = (bk, t-half) ----
    if (!last) {
        gsync();
        int bk = bid >> 1, half = bid & 1, b = bk >> 3, k = bk & 7;
        float x = g_slots[(size_t)bk * D_ + tid];
        float s = x, q = x * x;
        #pragma unroll
        for (int o = 16; o; o >>= 1) {
            s += __shfl_xor_sync(0xffffffffu, s, o);
            q += __shfl_xor_sync(0xffffffffu, q, o);
        }
        if ((tid & 31) == 0) { pool[tid >> 5] = s; pool[8 + (tid >> 5)] = q; }
        __syncthreads();
        float S = 0.0f, Q = 0.0f;
        #pragma unroll
        for (int i = 0; i < 8; i++) { S += pool[i]; Q += pool[8 + i]; }
        float m  = S * (1.0f / D_);
        float rstd = rsqrtf(Q * (1.0f / D_) - m * m + LN_EPS);
        float sv = (x - m) * rstd * ln_sl_g[tid] + ln_sl_b[tid];
        float* q_sh = pool + 16;
        q_sh[tid] = sv * tq[(size_t)k * 65536 + tid * 257];
        __syncthreads();
        int t = half * 128 + (tid >> 1);
        int hbase = (tid & 1) * 2;
        const float* tr = tk + (size_t)k * 65536 + (size_t)t * D_;
        #pragma unroll
        for (int hh = 0; hh < 2; hh++) {
            int h = hbase + hh;
            const float4* r4 = (const float4*)(tr + h * 64);
            const float4* q4 = (const float4*)(q_sh + h * 64);
            float a = 0.0f;
            #pragma unroll
            for (int j = 0; j < 16; j++) {
                float4 rv = r4[j], qv = q4[j];
                a += rv.x*qv.x + rv.y*qv.y + rv.z*qv.z + rv.w*qv.w;
            }
            g_w[((size_t)(b * 32 + k * 4 + h)) * D_ + t] = SCALEF * a;
        }
    }
}

// ------------------- launch -------------------
extern "C" void kernel_launch(void* const* d_in, const int* in_sizes, int n_in,
                              void* d_out, int out_size) {
    const float* emb   = (const float*)d_in[0];
    const float* noise = (const float*)d_in[1];
    const float* mu    = (const float*)d_in[2];
    const float* ls    = (const float*)d_in[3];
    const float* tk    = (const float*)d_in[4];
    const float* tq    = (const float*)d_in[5];
    const float* tv    = (const float*)d_in[6];
    const float* w_ih  = (const float*)d_in[7];
    const float* w_hh  = (const float*)d_in[8];
    const float* b_ih  = (const float*)d_in[9];
    const float* b_hh  = (const float*)d_in[10];
    const float* w1    = (const float*)d_in[11];
    const float* b1    = (const float*)d_in[12];
    const float* w2    = (const float*)d_in[13];
    const float* b2    = (const float*)d_in[14];
    const float* ln_in_g = (const float*)d_in[15];
    const float* ln_in_b = (const float*)d_in[16];
    const float* ln_sl_g = (const float*)d_in[17];
    const float* ln_sl_b = (const float*)d_in[18];
    const float* ln_ff_g = (const float*)d_in[19];
    const float* ln_ff_b = (const float*)d_in[20];

    float* out = (float*)d_out;
    float* vis = out + B_ * K_ * D_;            // slots first, then attn_vis

    const int ATTN_SMEM = (32 * WST + 32 * EST + 32 * 33 + 32 * 9) * 4;
    cudaFuncSetAttribute(k_attn, cudaFuncAttributeMaxDynamicSharedMemorySize, ATTN_SMEM);

    k_init_slots<<<128, 256>>>(mu, ls, noise);
    k_lnemb<<<B_ * N_ / 8, 256>>>(emb, ln_in_g, ln_in_b);
    k_w0<<<128, 256>>>(tq, tk, ln_sl_g, ln_sl_b);

    for (int it = 0; it < 3; it++) {
        k_attn<<<dim3(NT_, 16), 256, ATTN_SMEM>>>(vis, it == 2 ? 1 : 0);
        k_mega<<<NB2_, 256>>>(tq, tk, tv, w_ih, w_hh, b_ih, b_hh,
                              w1, b1, w2, b2, ln_sl_g, ln_sl_b, ln_ff_g, ln_ff_b,
                              it == 2 ? 1 : 0, out);
    }
}